// round 1
// baseline (speedup 1.0000x reference)
#include <cuda_runtime.h>
#include <cuda_bf16.h>

// Problem shape (fixed for this dataset instance)
//   sequence_output: [B=8, S=4096, H=1024] float32  -> in_sizes[0] = 33,554,432
//   sent_token_mask: [B, S]                int      -> in_sizes[1] = 32,768
// Output (assumed concatenated float32 buffer):
//   [0 .. B*S*H)          : sent_features  (identical copy of sequence_output)
//   [B*S*H .. B*S*H+B*S)  : topic_segment_ids as float
//
// topic_segment_ids:
//   inc[i]  = (label[i] == 0)                 (i over flattened B*S)
//   within  = exclusive prefix sum of inc
//   extra_off[b] = # of batches b' < b whose last label == 1
//   id[b,s] = within[b*S+s] + extra_off[b]

#define SCAN_THREADS 1024
#define MAX_B 64

__global__ __launch_bounds__(SCAN_THREADS)
void sent_feat_fused_kernel(const float4* __restrict__ src,
                            float4* __restrict__ dst,
                            long long n4,
                            const int* __restrict__ labels,
                            float* __restrict__ out_ids,
                            int B, int S, int n_tok)
{
    if (blockIdx.x == 0) {
        // ---------------- segment-id scan (single block) ----------------
        __shared__ int sums[SCAN_THREADS];
        __shared__ int extra_off[MAX_B];

        const int tid = threadIdx.x;
        const int per = n_tok / SCAN_THREADS;   // 32 for this shape
        const int base = tid * per;

        // Register-local flags + thread-local sum (vectorized int4 loads).
        int local[32];
        int s = 0;
        const int4* lab4 = reinterpret_cast<const int4*>(labels + base);
        #pragma unroll
        for (int v = 0; v < 32 / 4; v++) {
            int4 q = lab4[v];
            local[v * 4 + 0] = (q.x == 0);
            local[v * 4 + 1] = (q.y == 0);
            local[v * 4 + 2] = (q.z == 0);
            local[v * 4 + 3] = (q.w == 0);
            s += local[v * 4 + 0] + local[v * 4 + 1] + local[v * 4 + 2] + local[v * 4 + 3];
        }
        sums[tid] = s;

        // Per-batch "extra" exclusive offsets (B is tiny; thread 0 serial).
        if (tid == 0) {
            int acc = 0;
            for (int b = 0; b < B && b < MAX_B; b++) {
                extra_off[b] = acc;
                acc += (labels[b * S + S - 1] == 1);
            }
        }
        __syncthreads();

        // Hillis-Steele inclusive scan over the 1024 thread sums.
        #pragma unroll
        for (int off = 1; off < SCAN_THREADS; off <<= 1) {
            int v   = sums[tid];
            int add = (tid >= off) ? sums[tid - off] : 0;
            __syncthreads();
            sums[tid] = v + add;
            __syncthreads();
        }
        int run = sums[tid] - s;   // exclusive prefix for this thread

        // Emit ids (as float) with per-batch extra offset.
        #pragma unroll
        for (int i = 0; i < 32; i++) {
            int gi = base + i;
            int b  = gi / S;
            out_ids[gi] = (float)(run + extra_off[b]);
            run += local[i];
        }
    } else {
        // ---------------- bulk feature copy (float4 grid-stride) ----------------
        long long i = (long long)(blockIdx.x - 1) * blockDim.x + threadIdx.x;
        long long stride = (long long)(gridDim.x - 1) * blockDim.x;
        for (; i < n4; i += stride) {
            dst[i] = src[i];
        }
    }
}

extern "C" void kernel_launch(void* const* d_in, const int* in_sizes, int n_in,
                              void* d_out, int out_size)
{
    const float* seq    = (const float*)d_in[0];
    const int*   labels = (const int*)d_in[1];
    float*       out    = (float*)d_out;

    const long long n_feat = in_sizes[0];       // B*S*H
    const int       n_tok  = in_sizes[1];       // B*S
    const int       S      = 4096;
    const int       B      = n_tok / S;

    const long long n4 = n_feat / 4;            // float4 count (H=1024 -> divisible)

    // Enough blocks to saturate HBM: ~148 SMs, a few blocks each.
    int copy_blocks = 1184;                      // 148 * 8
    int grid = copy_blocks + 1;                  // +1 for the scan block

    sent_feat_fused_kernel<<<grid, SCAN_THREADS>>>(
        (const float4*)seq, (float4*)out, n4,
        labels, out + n_feat, B, S, n_tok);
}